// round 11
// baseline (speedup 1.0000x reference)
#include <cuda_runtime.h>
#include <math.h>

// GMM log-prob: out[n,k] = cst_k - 0.5 * sum_e (x_n . L_k[:,e] - mp[k,e])^2
// N=16384, K=200, D=64.

#define KCOMP 200
#define DF    64
#define TN    128      // n-rows per CTA
#define NTHREADS 256

typedef unsigned long long ull;

__device__ float g_mp[KCOMP * DF];   // means @ prec_chol, per k
__device__ float g_cst[KCOMP];       // logdet_k - 0.5*D*log(2pi)

// ---- packed f32x2 helpers (sm_103a) ----
__device__ __forceinline__ ull pack2_bcast(float a) {
    ull r;
    asm("mov.b64 %0, {%1, %1};" : "=l"(r) : "f"(a));
    return r;
}
__device__ __forceinline__ float2 unpack2(ull v) {
    float2 r;
    asm("mov.b64 {%0, %1}, %2;" : "=f"(r.x), "=f"(r.y) : "l"(v));
    return r;
}
__device__ __forceinline__ void fma2(ull& d, ull a, ull b) {
    asm("fma.rn.f32x2 %0, %1, %2, %0;" : "+l"(d) : "l"(a), "l"(b));
}

// ---------------------------------------------------------------------------
// Kernel 1: per-component constants. grid = K, block = 64 (one thread per e).
// ---------------------------------------------------------------------------
__global__ void gmm_precompute_kernel(const float* __restrict__ means,
                                      const float* __restrict__ pc) {
    const int k = blockIdx.x;
    const int e = threadIdx.x;
    const float* L = pc + (size_t)k * DF * DF;
    const float* mu = means + k * DF;

    float acc = 0.0f;
#pragma unroll 8
    for (int d = 0; d < DF; ++d)
        acc = fmaf(mu[d], L[d * DF + e], acc);
    g_mp[k * DF + e] = acc;

    // log-det: sum of log(diag)
    float lg = logf(L[e * DF + e]);
#pragma unroll
    for (int off = 16; off; off >>= 1)
        lg += __shfl_xor_sync(0xffffffffu, lg, off);
    __shared__ float s[2];
    if ((e & 31) == 0) s[e >> 5] = lg;
    __syncthreads();
    if (e == 0)
        g_cst[k] = (s[0] + s[1]) - 0.5f * DF * 1.8378770664093453f; // log(2*pi)
}

// ---------------------------------------------------------------------------
// Kernel 2: main compute. grid = (N/TN, K), block = 256.
// Warp layout: warp w -> et = w & 3 (e-slice of 16), nb = w >> 2 (row half).
// Thread owns rows r0 = nb*64 + 2*lane, r1 = r0+1, cols e0 = et*16 .. +15.
// smem: Ls[64*64] (16KB) + xs[64*128] transposed+swizzled (32KB) = 48KB.
// ---------------------------------------------------------------------------
__global__ void __launch_bounds__(NTHREADS, 2)
gmm_main_kernel(const float* __restrict__ x,
                const float* __restrict__ pc,
                float* __restrict__ out) {
    __shared__ float Ls[DF * DF];       // [d][e], row-contiguous
    __shared__ float xs[DF * TN];       // [d][n ^ (2*(d&15))]  transposed, swizzled

    const int tid = threadIdx.x;
    const int k  = blockIdx.y;
    const int n0 = blockIdx.x * TN;

    // --- load L tile (coalesced, conflict-free) ---
    {
        const float4* Lg4 = (const float4*)(pc + (size_t)k * DF * DF);
        float4* Ls4 = (float4*)Ls;
#pragma unroll
        for (int i = tid; i < DF * DF / 4; i += NTHREADS)
            Ls4[i] = Lg4[i];
    }
    // --- load x tile, transpose into smem with XOR swizzle ---
    {
        const float2* xg2 = (const float2*)(x + (size_t)n0 * DF);
#pragma unroll
        for (int i = tid; i < TN * (DF / 2); i += NTHREADS) {
            int n = i >> 5;          // row 0..127
            int j = i & 31;          // float2 index within row
            int d = 2 * j;
            float2 v = xg2[n * 32 + j];
            xs[(d    ) * TN + (n ^ (2 * ( d      & 15)))] = v.x;
            xs[(d + 1) * TN + (n ^ (2 * ((d + 1) & 15)))] = v.y;
        }
    }
    __syncthreads();

    const int warp = tid >> 5, lane = tid & 31;
    const int et = warp & 3, nb = warp >> 2;
    const int e0 = et * 16;
    const int r0 = nb * 64 + 2 * lane;   // even

    ull acc0[8], acc1[8];
#pragma unroll
    for (int j = 0; j < 8; ++j) { acc0[j] = 0ull; acc1[j] = 0ull; }

#pragma unroll 16
    for (int d = 0; d < DF; ++d) {
        const int sw = 2 * (d & 15);
        // one LDS.64 fetches x[r0][d] and x[r1][d]
        float2 xv = *(const float2*)(xs + d * TN + (r0 ^ sw));
        ull xa = pack2_bcast(xv.x);
        ull xb = pack2_bcast(xv.y);
        // L[d][e0..e0+15]: full warp broadcast, 4x LDS.128
        const ulonglong2* lp = (const ulonglong2*)(Ls + d * DF + e0);
        ulonglong2 l0 = lp[0], l1 = lp[1], l2 = lp[2], l3 = lp[3];
        ull lv[8] = { l0.x, l0.y, l1.x, l1.y, l2.x, l2.y, l3.x, l3.y };
#pragma unroll
        for (int j = 0; j < 8; ++j) {
            fma2(acc0[j], xa, lv[j]);
            fma2(acc1[j], xb, lv[j]);
        }
    }

    // --- epilogue: q = sum_e (y - mp)^2 for each of the 2 rows ---
    const float2* mp2 = (const float2*)(g_mp + k * DF + e0);
    float q0 = 0.0f, q1 = 0.0f;
#pragma unroll
    for (int j = 0; j < 8; ++j) {
        float2 m  = mp2[j];
        float2 y0 = unpack2(acc0[j]);
        float2 y1 = unpack2(acc1[j]);
        float t;
        t = y0.x - m.x; q0 = fmaf(t, t, q0);
        t = y0.y - m.y; q0 = fmaf(t, t, q0);
        t = y1.x - m.x; q1 = fmaf(t, t, q1);
        t = y1.y - m.y; q1 = fmaf(t, t, q1);
    }

    // combine the 4 e-slice warps (reuse xs as scratch after the mainloop)
    __syncthreads();
    float2* red = (float2*)xs;   // [4][64] float2
    red[et * 64 + nb * 32 + lane] = make_float2(q0, q1);
    __syncthreads();

    if (tid < 64) {
        float2 s0 = red[tid], s1 = red[64 + tid], s2 = red[128 + tid], s3 = red[192 + tid];
        float qa = (s0.x + s1.x) + (s2.x + s3.x);
        float qb = (s0.y + s1.y) + (s2.y + s3.y);
        int nbb = tid >> 5, ln = tid & 31;
        int rr0 = nbb * 64 + 2 * ln;
        float cst = g_cst[k];
        out[(n0 + rr0    ) * KCOMP + k] = cst - 0.5f * qa;
        out[(n0 + rr0 + 1) * KCOMP + k] = cst - 0.5f * qb;
    }
}

// ---------------------------------------------------------------------------
extern "C" void kernel_launch(void* const* d_in, const int* in_sizes, int n_in,
                              void* d_out, int out_size) {
    const float* x     = (const float*)d_in[0];  // [16384, 64]
    const float* means = (const float*)d_in[1];  // [200, 64]
    const float* pc    = (const float*)d_in[2];  // [200, 64, 64]
    float* out = (float*)d_out;                  // [16384, 200]

    gmm_precompute_kernel<<<KCOMP, 64>>>(means, pc);

    dim3 grid(16384 / TN, KCOMP);  // (128, 200)
    gmm_main_kernel<<<grid, NTHREADS>>>(x, pc, out);
}

// round 13
// speedup vs baseline: 2.1637x; 2.1637x over previous
#include <cuda_runtime.h>
#include <cuda_bf16.h>
#include <math.h>
#include <cstdint>

// GMM log-prob via mma.sync (HMMA, family-portable) bf16-split GEMM.
// out[n,k] = cst_k - 0.5 * sum_e (sum_d x[n,d] L_k[d,e] - mp[k,e])^2
// N=16384, K=200, D=64.

#define KCOMP 200
#define DF    64
#define NROWS 16384
#define TN    128
#define NTHREADS 256

// ---------------- device globals (no allocs allowed) ----------------
__device__ float g_mp[KCOMP * DF];
__device__ float g_cst[KCOMP];
__device__ __align__(16) __nv_bfloat16 g_xhi[NROWS * DF];
__device__ __align__(16) __nv_bfloat16 g_xlo[NROWS * DF];
// L transposed to [k][e][d] (row = e, 64 bf16 = 128B row), bf16 hi/lo.
__device__ __align__(16) __nv_bfloat16 g_LThi[KCOMP * DF * DF];
__device__ __align__(16) __nv_bfloat16 g_LTlo[KCOMP * DF * DF];

// ---------------- smem layout (bytes, all tiles 1024-aligned) ----------------
#define SM_XHI    0            // 16 KB
#define SM_XLO    16384        // 16 KB
#define SM_LBUF   32768
#define LSTRIDE   17408        // Lhi 8K | Llo 8K | mp 256B | cst 4B | pad
#define L_LO_OFF  8192
#define L_MP_OFF  16384
#define SMEM_TOTAL (SM_LBUF + 2 * LSTRIDE)   // 67584

// ---------------- helpers ----------------
__device__ __forceinline__ uint32_t smem_u32(const void* p) {
    uint32_t a;
    asm("{ .reg .u64 t; cvta.to.shared.u64 t, %1; cvt.u32.u64 %0, t; }" : "=r"(a) : "l"(p));
    return a;
}
__device__ __forceinline__ uint32_t sw128(uint32_t off) { return off ^ ((off >> 3) & 0x70); }

__device__ __forceinline__ void cp16(uint32_t dst, const void* src) {
    asm volatile("cp.async.ca.shared.global [%0], [%1], 16;" :: "r"(dst), "l"(src) : "memory");
}
__device__ __forceinline__ void cp4(uint32_t dst, const void* src) {
    asm volatile("cp.async.ca.shared.global [%0], [%1], 4;" :: "r"(dst), "l"(src) : "memory");
}
__device__ __forceinline__ void cp_commit() { asm volatile("cp.async.commit_group;" ::: "memory"); }
__device__ __forceinline__ void cp_wait1()  { asm volatile("cp.async.wait_group 1;" ::: "memory"); }

__device__ __forceinline__ void ldsm4(uint32_t* r, uint32_t addr) {
    asm volatile("ldmatrix.sync.aligned.m8n8.x4.shared.b16 {%0,%1,%2,%3}, [%4];"
                 : "=r"(r[0]), "=r"(r[1]), "=r"(r[2]), "=r"(r[3]) : "r"(addr));
}
__device__ __forceinline__ void mma16816(float* c, const uint32_t* a, uint32_t b0, uint32_t b1) {
    asm volatile("mma.sync.aligned.m16n8k16.row.col.f32.bf16.bf16.f32 "
                 "{%0,%1,%2,%3}, {%4,%5,%6,%7}, {%8,%9}, {%0,%1,%2,%3};"
                 : "+f"(c[0]), "+f"(c[1]), "+f"(c[2]), "+f"(c[3])
                 : "r"(a[0]), "r"(a[1]), "r"(a[2]), "r"(a[3]), "r"(b0), "r"(b1));
}

// ---------------- precompute kernels ----------------
__global__ void gmm_precompute_kernel(const float* __restrict__ means,
                                      const float* __restrict__ pc) {
    const int k = blockIdx.x;
    const int e = threadIdx.x;
    const float* L = pc + (size_t)k * DF * DF;
    const float* mu = means + k * DF;
    float acc = 0.0f;
#pragma unroll 8
    for (int d = 0; d < DF; ++d) acc = fmaf(mu[d], L[d * DF + e], acc);
    g_mp[k * DF + e] = acc;
    float lg = logf(L[e * DF + e]);
#pragma unroll
    for (int off = 16; off; off >>= 1) lg += __shfl_xor_sync(0xffffffffu, lg, off);
    __shared__ float s[2];
    if ((e & 31) == 0) s[e >> 5] = lg;
    __syncthreads();
    if (e == 0) g_cst[k] = (s[0] + s[1]) - 0.5f * DF * 1.8378770664093453f;
}

__global__ void split_x_kernel(const float* __restrict__ x) {
    int i = blockIdx.x * 256 + threadIdx.x;
    if (i < NROWS * DF) {
        float v = x[i];
        __nv_bfloat16 hi = __float2bfloat16(v);
        g_xhi[i] = hi;
        g_xlo[i] = __float2bfloat16(v - __bfloat162float(hi));
    }
}

__global__ void split_L_kernel(const float* __restrict__ pc) {
    const int k = blockIdx.x;
    for (int idx = threadIdx.x; idx < DF * DF; idx += 256) {
        int d = idx >> 6, e = idx & 63;
        float v = pc[(size_t)k * DF * DF + idx];        // [d][e]
        __nv_bfloat16 hi = __float2bfloat16(v);
        g_LThi[(size_t)k * DF * DF + e * DF + d] = hi;  // [e][d]
        g_LTlo[(size_t)k * DF * DF + e * DF + d] = __float2bfloat16(v - __bfloat162float(hi));
    }
}

// ---------------- main HMMA kernel ----------------
__device__ __forceinline__ void load_ltile(uint32_t sb, int k, int b) {
    uint32_t base = sb + SM_LBUF + b * LSTRIDE;
    const char* sh = (const char*)g_LThi + (size_t)k * DF * DF * 2;
    const char* sl = (const char*)g_LTlo + (size_t)k * DF * DF * 2;
    int tid = threadIdx.x;
#pragma unroll
    for (int i = 0; i < 2; i++) {
        int c = tid + i * NTHREADS;          // 0..511 chunks of 16B (8 KB)
        uint32_t d = sw128((uint32_t)c * 16);
        cp16(base + d, sh + c * 16);
        cp16(base + L_LO_OFF + d, sl + c * 16);
    }
    if (tid < 16)
        cp16(base + L_MP_OFF + tid * 16, (const char*)g_mp + (size_t)k * DF * 4 + tid * 16);
    if (tid == 16)
        cp4(base + L_MP_OFF + 256, (const char*)g_cst + (size_t)k * 4);
}

__global__ void __launch_bounds__(NTHREADS, 1)
gmm_hmma_kernel(float* __restrict__ out) {
    extern __shared__ __align__(1024) char smem[];
    uint32_t sb = smem_u32(smem);
    const int tid = threadIdx.x, wid = tid >> 5, lane = tid & 31;
    const int n0 = blockIdx.x * TN;

    // prologue: x tile (hi+lo, 16KB each) + L tiles for k=0,1
    {
        const char* xh = (const char*)g_xhi + (size_t)n0 * DF * 2;
        const char* xl = (const char*)g_xlo + (size_t)n0 * DF * 2;
#pragma unroll
        for (int i = 0; i < 4; i++) {
            int c = tid + i * NTHREADS;      // 0..1023 chunks of 16B
            uint32_t d = sw128((uint32_t)c * 16);
            cp16(sb + SM_XHI + d, xh + c * 16);
            cp16(sb + SM_XLO + d, xl + c * 16);
        }
    }
    load_ltile(sb, 0, 0);
    cp_commit();                 // G0 = X + L0
    load_ltile(sb, 1, 1);
    cp_commit();                 // G1 = L1
    cp_wait1();                  // G0 complete
    __syncthreads();

    // A fragments (x tile), loaded once: 4 k-steps x (hi,lo)
    uint32_t ah[4][4], al[4][4];
    {
        uint32_t arow = (uint32_t)(wid * 16 + (lane & 15));
        uint32_t acol = (uint32_t)((lane >> 4) * 16);
#pragma unroll
        for (int kk = 0; kk < 4; kk++) {
            uint32_t off = sw128(arow * 128 + kk * 32 + acol);
            ldsm4(ah[kk], sb + SM_XHI + off);
            ldsm4(al[kk], sb + SM_XLO + off);
        }
    }

    const uint32_t brow = (lane & 7) + ((lane >> 4) << 3);
    const uint32_t bcol = ((lane >> 3) & 1) * 16;

    for (int k = 0; k < KCOMP; ++k) {
        const int b = k & 1;
        cp_wait1();              // buffer b for component k is resident
        __syncthreads();

        const float* mps = (const float*)(smem + SM_LBUF + b * LSTRIDE + L_MP_OFF);
        // init acc = -mp  =>  GEMM result is directly y - mp
        float acc[8][4];
#pragma unroll
        for (int nt = 0; nt < 8; nt++) {
            float2 m = *(const float2*)(mps + nt * 8 + 2 * (lane & 3));
            acc[nt][0] = -m.x; acc[nt][1] = -m.y;
            acc[nt][2] = -m.x; acc[nt][3] = -m.y;
        }

        const uint32_t lb = sb + SM_LBUF + b * LSTRIDE;
#pragma unroll
        for (int kk = 0; kk < 4; kk++) {
            uint32_t bh[16], bl[16];
#pragma unroll
            for (int p = 0; p < 4; p++) {    // each ldsm4 covers 2 n-tiles
                uint32_t off = sw128((brow + p * 16) * 128 + kk * 32 + bcol);
                ldsm4(bh + 4 * p, lb + off);
                ldsm4(bl + 4 * p, lb + L_LO_OFF + off);
            }
#pragma unroll
            for (int nt = 0; nt < 8; nt++) {
                mma16816(acc[nt], ah[kk], bh[2 * nt], bh[2 * nt + 1]);  // hi*hi
                mma16816(acc[nt], al[kk], bh[2 * nt], bh[2 * nt + 1]);  // lo*hi
                mma16816(acc[nt], ah[kk], bl[2 * nt], bl[2 * nt + 1]);  // hi*lo
            }
        }

        // epilogue: q = sum_e (y-mp)^2 per row (2 rows/lane), quad reduce
        float q0 = 0.f, q1 = 0.f;
#pragma unroll
        for (int nt = 0; nt < 8; nt++) {
            q0 = fmaf(acc[nt][0], acc[nt][0], q0);
            q0 = fmaf(acc[nt][1], acc[nt][1], q0);
            q1 = fmaf(acc[nt][2], acc[nt][2], q1);
            q1 = fmaf(acc[nt][3], acc[nt][3], q1);
        }
        q0 += __shfl_xor_sync(0xffffffffu, q0, 1);
        q0 += __shfl_xor_sync(0xffffffffu, q0, 2);
        q1 += __shfl_xor_sync(0xffffffffu, q1, 1);
        q1 += __shfl_xor_sync(0xffffffffu, q1, 2);

        float cst = mps[64];
        if ((lane & 3) == 0) {
            int row = n0 + wid * 16 + (lane >> 2);
            out[(size_t)row * KCOMP + k]       = cst - 0.5f * q0;
            out[(size_t)(row + 8) * KCOMP + k] = cst - 0.5f * q1;
        }

        __syncthreads();         // everyone done reading buffer b
        if (k + 2 < KCOMP) load_ltile(sb, k + 2, b);
        cp_commit();
    }
}

// ---------------------------------------------------------------------------
extern "C" void kernel_launch(void* const* d_in, const int* in_sizes, int n_in,
                              void* d_out, int out_size) {
    const float* x     = (const float*)d_in[0];  // [16384, 64]
    const float* means = (const float*)d_in[1];  // [200, 64]
    const float* pc    = (const float*)d_in[2];  // [200, 64, 64]
    float* out = (float*)d_out;                  // [16384, 200]

    cudaFuncSetAttribute(gmm_hmma_kernel,
                         cudaFuncAttributeMaxDynamicSharedMemorySize, SMEM_TOTAL);

    gmm_precompute_kernel<<<KCOMP, 64>>>(means, pc);
    split_x_kernel<<<(NROWS * DF + 255) / 256, 256>>>(x);
    split_L_kernel<<<KCOMP, 256>>>(pc);
    gmm_hmma_kernel<<<NROWS / TN, NTHREADS, SMEM_TOTAL>>>(out);
}

// round 14
// speedup vs baseline: 3.4519x; 1.5953x over previous
#include <cuda_runtime.h>
#include <cuda_bf16.h>
#include <math.h>
#include <cstdint>

// GMM log-prob via mma.sync bf16 GEMM (x split hi/lo, L bf16).
// out[n,k] = cst_k - 0.5 * sum_e (sum_d x[n,d] L_k[d,e] - mp[k,e])^2
// N=16384, K=200, D=64.

#define KCOMP 200
#define KSPLIT 2
#define KC_PER (KCOMP / KSPLIT)   // 100
#define DF    64
#define NROWS 16384
#define TN    128
#define NTHREADS 256

// ---------------- device globals ----------------
__device__ float g_mp[KCOMP * DF];
__device__ float g_cst[KCOMP];
__device__ __align__(16) __nv_bfloat16 g_xhi[NROWS * DF];
__device__ __align__(16) __nv_bfloat16 g_xlo[NROWS * DF];
// L transposed to [k][e][d] (row = e, 64 bf16 = 128B row).
__device__ __align__(16) __nv_bfloat16 g_LT[KCOMP * DF * DF];

// ---------------- smem layout ----------------
// X hi (16K) | X lo (16K) | 4 stages x (L 8K + mp 256B + cst 4B + pad)
#define SM_XHI    0
#define SM_XLO    16384
#define SM_LBUF   32768
#define LSTRIDE   8576            // 8192 L + 256 mp + 4 cst + pad (128-aligned)
#define L_MP_OFF  8192
#define NSTAGE    4
#define SMEM_TOTAL (SM_LBUF + NSTAGE * LSTRIDE)   // 67072

// ---------------- helpers ----------------
__device__ __forceinline__ uint32_t smem_u32(const void* p) {
    uint32_t a;
    asm("{ .reg .u64 t; cvta.to.shared.u64 t, %1; cvt.u32.u64 %0, t; }" : "=r"(a) : "l"(p));
    return a;
}
__device__ __forceinline__ uint32_t sw128(uint32_t off) { return off ^ ((off >> 3) & 0x70); }

__device__ __forceinline__ void cp16(uint32_t dst, const void* src) {
    asm volatile("cp.async.ca.shared.global [%0], [%1], 16;" :: "r"(dst), "l"(src) : "memory");
}
__device__ __forceinline__ void cp4(uint32_t dst, const void* src) {
    asm volatile("cp.async.ca.shared.global [%0], [%1], 4;" :: "r"(dst), "l"(src) : "memory");
}
__device__ __forceinline__ void cp_commit() { asm volatile("cp.async.commit_group;" ::: "memory"); }
__device__ __forceinline__ void cp_wait2()  { asm volatile("cp.async.wait_group 2;" ::: "memory"); }

__device__ __forceinline__ void ldsm4(uint32_t* r, uint32_t addr) {
    asm volatile("ldmatrix.sync.aligned.m8n8.x4.shared.b16 {%0,%1,%2,%3}, [%4];"
                 : "=r"(r[0]), "=r"(r[1]), "=r"(r[2]), "=r"(r[3]) : "r"(addr));
}
__device__ __forceinline__ void mma16816(float* c, const uint32_t* a, uint32_t b0, uint32_t b1) {
    asm volatile("mma.sync.aligned.m16n8k16.row.col.f32.bf16.bf16.f32 "
                 "{%0,%1,%2,%3}, {%4,%5,%6,%7}, {%8,%9}, {%0,%1,%2,%3};"
                 : "+f"(c[0]), "+f"(c[1]), "+f"(c[2]), "+f"(c[3])
                 : "r"(a[0]), "r"(a[1]), "r"(a[2]), "r"(a[3]), "r"(b0), "r"(b1));
}

// ---------------- precompute kernels ----------------
__global__ void gmm_precompute_kernel(const float* __restrict__ means,
                                      const float* __restrict__ pc) {
    const int k = blockIdx.x;
    const int e = threadIdx.x;
    const float* L = pc + (size_t)k * DF * DF;
    const float* mu = means + k * DF;
    float acc = 0.0f;
#pragma unroll 8
    for (int d = 0; d < DF; ++d) acc = fmaf(mu[d], L[d * DF + e], acc);
    g_mp[k * DF + e] = acc;
    float lg = logf(L[e * DF + e]);
#pragma unroll
    for (int off = 16; off; off >>= 1) lg += __shfl_xor_sync(0xffffffffu, lg, off);
    __shared__ float s[2];
    if ((e & 31) == 0) s[e >> 5] = lg;
    __syncthreads();
    if (e == 0) g_cst[k] = (s[0] + s[1]) - 0.5f * DF * 1.8378770664093453f;
}

__global__ void split_x_kernel(const float* __restrict__ x) {
    int i = blockIdx.x * 256 + threadIdx.x;
    if (i < NROWS * DF) {
        float v = x[i];
        __nv_bfloat16 hi = __float2bfloat16(v);
        g_xhi[i] = hi;
        g_xlo[i] = __float2bfloat16(v - __bfloat162float(hi));
    }
}

__global__ void split_L_kernel(const float* __restrict__ pc) {
    const int k = blockIdx.x;
    for (int idx = threadIdx.x; idx < DF * DF; idx += 256) {
        int d = idx >> 6, e = idx & 63;
        float v = pc[(size_t)k * DF * DF + idx];        // [d][e]
        g_LT[(size_t)k * DF * DF + e * DF + d] = __float2bfloat16(v);  // [e][d]
    }
}

// ---------------- main HMMA kernel ----------------
__device__ __forceinline__ void load_ltile(uint32_t sb, int kg, int st) {
    uint32_t base = sb + SM_LBUF + st * LSTRIDE;
    const char* sh = (const char*)g_LT + (size_t)kg * DF * DF * 2;
    int tid = threadIdx.x;
#pragma unroll
    for (int i = 0; i < 2; i++) {
        int c = tid + i * NTHREADS;          // 0..511 chunks of 16B (8 KB)
        cp16(base + sw128((uint32_t)c * 16), sh + c * 16);
    }
    if (tid < 16)
        cp16(base + L_MP_OFF + tid * 16, (const char*)g_mp + (size_t)kg * DF * 4 + tid * 16);
    if (tid == 16)
        cp4(base + L_MP_OFF + 256, (const char*)g_cst + (size_t)kg * 4);
}

__global__ void __launch_bounds__(NTHREADS, 2)
gmm_hmma_kernel(float* __restrict__ out) {
    extern __shared__ __align__(1024) char smem[];
    uint32_t sb = smem_u32(smem);
    const int tid = threadIdx.x, wid = tid >> 5, lane = tid & 31;
    const int n0 = blockIdx.x * TN;
    const int kbase = blockIdx.y * KC_PER;

    // prologue: X tile (hi+lo) + L stages 0..2
    {
        const char* xh = (const char*)g_xhi + (size_t)n0 * DF * 2;
        const char* xl = (const char*)g_xlo + (size_t)n0 * DF * 2;
#pragma unroll
        for (int i = 0; i < 4; i++) {
            int c = tid + i * NTHREADS;      // 0..1023 chunks of 16B
            uint32_t d = sw128((uint32_t)c * 16);
            cp16(sb + SM_XHI + d, xh + c * 16);
            cp16(sb + SM_XLO + d, xl + c * 16);
        }
    }
    load_ltile(sb, kbase + 0, 0);
    cp_commit();                 // G0 = X + L0
    load_ltile(sb, kbase + 1, 1);
    cp_commit();                 // G1 = L1
    load_ltile(sb, kbase + 2, 2);
    cp_commit();                 // G2 = L2

    uint32_t ah[4][4], al[4][4];
    const uint32_t brow = (lane & 7) + ((lane >> 4) << 3);
    const uint32_t bcol = ((lane >> 3) & 1) * 16;

    for (int k = 0; k < KC_PER; ++k) {
        const int st = k & (NSTAGE - 1);
        cp_wait2();              // stage k resident (3 groups in flight -> 2)
        __syncthreads();         // also: all warps done reading stage k-1

        if (k == 0) {
            // A fragments (x tile), loaded once
            uint32_t arow = (uint32_t)(wid * 16 + (lane & 15));
            uint32_t acol = (uint32_t)((lane >> 4) * 16);
#pragma unroll
            for (int kk = 0; kk < 4; kk++) {
                uint32_t off = sw128(arow * 128 + kk * 32 + acol);
                ldsm4(ah[kk], sb + SM_XHI + off);
                ldsm4(al[kk], sb + SM_XLO + off);
            }
        }

        // prefetch stage k+3 (overwrites stage k-1; safe after the sync above)
        if (k + 3 < KC_PER) load_ltile(sb, kbase + k + 3, (k + 3) & (NSTAGE - 1));
        cp_commit();             // always commit (empty group at tail keeps invariant)

        const float* mps = (const float*)(smem + SM_LBUF + st * LSTRIDE + L_MP_OFF);
        // init acc = -mp  =>  GEMM result is directly y - mp
        float acc[8][4];
#pragma unroll
        for (int nt = 0; nt < 8; nt++) {
            float2 m = *(const float2*)(mps + nt * 8 + 2 * (lane & 3));
            acc[nt][0] = -m.x; acc[nt][1] = -m.y;
            acc[nt][2] = -m.x; acc[nt][3] = -m.y;
        }

        const uint32_t lb = sb + SM_LBUF + st * LSTRIDE;
#pragma unroll
        for (int kk = 0; kk < 4; kk++) {
            uint32_t bh[16];
#pragma unroll
            for (int p = 0; p < 4; p++)      // each ldsm4 covers 2 n-tiles
                ldsm4(bh + 4 * p, lb + sw128((brow + p * 16) * 128 + kk * 32 + bcol));
#pragma unroll
            for (int nt = 0; nt < 8; nt++)
                mma16816(acc[nt], ah[kk], bh[2 * nt], bh[2 * nt + 1]);  // xhi * L
#pragma unroll
            for (int nt = 0; nt < 8; nt++)
                mma16816(acc[nt], al[kk], bh[2 * nt], bh[2 * nt + 1]);  // xlo * L
        }

        // epilogue: q = sum_e (y-mp)^2 per row (2 rows/lane), quad reduce
        float q0 = 0.f, q1 = 0.f;
#pragma unroll
        for (int nt = 0; nt < 8; nt++) {
            q0 = fmaf(acc[nt][0], acc[nt][0], q0);
            q0 = fmaf(acc[nt][1], acc[nt][1], q0);
            q1 = fmaf(acc[nt][2], acc[nt][2], q1);
            q1 = fmaf(acc[nt][3], acc[nt][3], q1);
        }
        q0 += __shfl_xor_sync(0xffffffffu, q0, 1);
        q0 += __shfl_xor_sync(0xffffffffu, q0, 2);
        q1 += __shfl_xor_sync(0xffffffffu, q1, 1);
        q1 += __shfl_xor_sync(0xffffffffu, q1, 2);

        float cst = mps[64];
        if ((lane & 3) == 0) {
            int row = n0 + wid * 16 + (lane >> 2);
            int kg = kbase + k;
            out[(size_t)row * KCOMP + kg]       = cst - 0.5f * q0;
            out[(size_t)(row + 8) * KCOMP + kg] = cst - 0.5f * q1;
        }
    }
}

// ---------------------------------------------------------------------------
extern "C" void kernel_launch(void* const* d_in, const int* in_sizes, int n_in,
                              void* d_out, int out_size) {
    const float* x     = (const float*)d_in[0];  // [16384, 64]
    const float* means = (const float*)d_in[1];  // [200, 64]
    const float* pc    = (const float*)d_in[2];  // [200, 64, 64]
    float* out = (float*)d_out;                  // [16384, 200]

    cudaFuncSetAttribute(gmm_hmma_kernel,
                         cudaFuncAttributeMaxDynamicSharedMemorySize, SMEM_TOTAL);

    gmm_precompute_kernel<<<KCOMP, 64>>>(means, pc);
    split_x_kernel<<<(NROWS * DF + 255) / 256, 256>>>(x);
    split_L_kernel<<<KCOMP, 256>>>(pc);

    dim3 grid(NROWS / TN, KSPLIT);   // (128, 2) = 256 CTAs
    gmm_hmma_kernel<<<grid, NTHREADS, SMEM_TOTAL>>>(out);
}

// round 15
// speedup vs baseline: 5.5784x; 1.6160x over previous
#include <cuda_runtime.h>
#include <cuda_fp16.h>
#include <math.h>
#include <cstdint>

// GMM log-prob via single-pass fp16 mma.sync GEMM (fp32 accumulate).
// out[n,k] = cst_k - 0.5 * sum_e (sum_d x[n,d] L_k[d,e] - mp[k,e])^2
// N=16384, K=200, D=64.

#define KCOMP 200
#define KSPLIT 8
#define KC_PER (KCOMP / KSPLIT)   // 25
#define DF    64
#define NROWS 16384
#define TN    256                 // rows per CTA (8 warps x 32 rows)
#define NTHREADS 256

// ---------------- device globals ----------------
__device__ float g_mp[KCOMP * DF];
__device__ float g_cst[KCOMP];
__device__ __align__(16) __half g_xh[NROWS * DF];
// L transposed to [k][e][d] (row = e, 64 fp16 = 128B row).
__device__ __align__(16) __half g_LT[KCOMP * DF * DF];

// ---------------- smem layout ----------------
// X (32K) | 4 stages x (L 8K + mp 256B + cst 4B + pad)
#define SM_X      0
#define SM_LBUF   32768
#define LSTRIDE   8576
#define L_MP_OFF  8192
#define NSTAGE    4
#define SMEM_TOTAL (SM_LBUF + NSTAGE * LSTRIDE)   // 67072

// ---------------- helpers ----------------
__device__ __forceinline__ uint32_t smem_u32(const void* p) {
    uint32_t a;
    asm("{ .reg .u64 t; cvta.to.shared.u64 t, %1; cvt.u32.u64 %0, t; }" : "=r"(a) : "l"(p));
    return a;
}
__device__ __forceinline__ uint32_t sw128(uint32_t off) { return off ^ ((off >> 3) & 0x70); }

__device__ __forceinline__ void cp16(uint32_t dst, const void* src) {
    asm volatile("cp.async.ca.shared.global [%0], [%1], 16;" :: "r"(dst), "l"(src) : "memory");
}
__device__ __forceinline__ void cp4(uint32_t dst, const void* src) {
    asm volatile("cp.async.ca.shared.global [%0], [%1], 4;" :: "r"(dst), "l"(src) : "memory");
}
__device__ __forceinline__ void cp_commit() { asm volatile("cp.async.commit_group;" ::: "memory"); }
__device__ __forceinline__ void cp_wait2()  { asm volatile("cp.async.wait_group 2;" ::: "memory"); }

__device__ __forceinline__ void ldsm4(uint32_t* r, uint32_t addr) {
    asm volatile("ldmatrix.sync.aligned.m8n8.x4.shared.b16 {%0,%1,%2,%3}, [%4];"
                 : "=r"(r[0]), "=r"(r[1]), "=r"(r[2]), "=r"(r[3]) : "r"(addr));
}
__device__ __forceinline__ void mma16816(float* c, const uint32_t* a, uint32_t b0, uint32_t b1) {
    asm volatile("mma.sync.aligned.m16n8k16.row.col.f32.f16.f16.f32 "
                 "{%0,%1,%2,%3}, {%4,%5,%6,%7}, {%8,%9}, {%0,%1,%2,%3};"
                 : "+f"(c[0]), "+f"(c[1]), "+f"(c[2]), "+f"(c[3])
                 : "r"(a[0]), "r"(a[1]), "r"(a[2]), "r"(a[3]), "r"(b0), "r"(b1));
}

// ---------------- precompute kernels ----------------
__global__ void gmm_precompute_kernel(const float* __restrict__ means,
                                      const float* __restrict__ pc) {
    const int k = blockIdx.x;
    const int e = threadIdx.x;
    const float* L = pc + (size_t)k * DF * DF;
    const float* mu = means + k * DF;
    float acc = 0.0f;
#pragma unroll 8
    for (int d = 0; d < DF; ++d) acc = fmaf(mu[d], L[d * DF + e], acc);
    g_mp[k * DF + e] = acc;
    float lg = logf(L[e * DF + e]);
#pragma unroll
    for (int off = 16; off; off >>= 1) lg += __shfl_xor_sync(0xffffffffu, lg, off);
    __shared__ float s[2];
    if ((e & 31) == 0) s[e >> 5] = lg;
    __syncthreads();
    if (e == 0) g_cst[k] = (s[0] + s[1]) - 0.5f * DF * 1.8378770664093453f;
}

__global__ void split_x_kernel(const float* __restrict__ x) {
    int i = blockIdx.x * 256 + threadIdx.x;
    if (i < NROWS * DF) g_xh[i] = __float2half(x[i]);
}

__global__ void split_L_kernel(const float* __restrict__ pc) {
    const int k = blockIdx.x;
    for (int idx = threadIdx.x; idx < DF * DF; idx += 256) {
        int d = idx >> 6, e = idx & 63;
        g_LT[(size_t)k * DF * DF + e * DF + d] = __float2half(pc[(size_t)k * DF * DF + idx]);
    }
}

// ---------------- main HMMA kernel ----------------
__device__ __forceinline__ void load_ltile(uint32_t sb, int kg, int st) {
    uint32_t base = sb + SM_LBUF + st * LSTRIDE;
    const char* sh = (const char*)g_LT + (size_t)kg * DF * DF * 2;
    int tid = threadIdx.x;
#pragma unroll
    for (int i = 0; i < 2; i++) {
        int c = tid + i * NTHREADS;          // 0..511 chunks of 16B (8 KB)
        cp16(base + sw128((uint32_t)c * 16), sh + c * 16);
    }
    if (tid < 16)
        cp16(base + L_MP_OFF + tid * 16, (const char*)g_mp + (size_t)kg * DF * 4 + tid * 16);
    if (tid == 16)
        cp4(base + L_MP_OFF + 256, (const char*)g_cst + (size_t)kg * 4);
}

__global__ void __launch_bounds__(NTHREADS, 2)
gmm_hmma_kernel(float* __restrict__ out) {
    extern __shared__ __align__(1024) char smem[];
    uint32_t sb = smem_u32(smem);
    const int tid = threadIdx.x, wid = tid >> 5, lane = tid & 31;
    const int n0 = blockIdx.x * TN;
    const int kbase = blockIdx.y * KC_PER;

    // prologue: X tile (32 KB) + L stages 0..2
    {
        const char* xh = (const char*)g_xh + (size_t)n0 * DF * 2;
#pragma unroll
        for (int i = 0; i < 8; i++) {
            int c = tid + i * NTHREADS;      // 0..2047 chunks of 16B
            cp16(sb + SM_X + sw128((uint32_t)c * 16), xh + c * 16);
        }
    }
    load_ltile(sb, kbase + 0, 0);
    cp_commit();                 // G0 = X + L0
    load_ltile(sb, kbase + 1, 1);
    cp_commit();                 // G1 = L1
    load_ltile(sb, kbase + 2, 2);
    cp_commit();                 // G2 = L2

    uint32_t ah[2][4][4];        // [m-tile][k-step][frag]
    const uint32_t brow = (lane & 7) + ((lane >> 4) << 3);
    const uint32_t bcol = ((lane >> 3) & 1) * 16;

    for (int k = 0; k < KC_PER; ++k) {
        const int st = k & (NSTAGE - 1);
        cp_wait2();              // stage k resident
        __syncthreads();         // + all warps done reading stage k-1

        if (k == 0) {            // A fragments: 2 m-tiles x 4 k-steps, loaded once
            uint32_t acol = (uint32_t)((lane >> 4) * 16);
#pragma unroll
            for (int mt = 0; mt < 2; mt++) {
                uint32_t arow = (uint32_t)(wid * 32 + mt * 16 + (lane & 15));
#pragma unroll
                for (int kk = 0; kk < 4; kk++)
                    ldsm4(ah[mt][kk], sb + SM_X + sw128(arow * 128 + kk * 32 + acol));
            }
        }

        if (k + 3 < KC_PER) load_ltile(sb, kbase + k + 3, (k + 3) & (NSTAGE - 1));
        cp_commit();             // empty group at tail keeps wait invariant

        const uint32_t lb = sb + SM_LBUF + st * LSTRIDE;
        const float* mps = (const float*)(smem + SM_LBUF + st * LSTRIDE + L_MP_OFF);

        float q[4] = {0.f, 0.f, 0.f, 0.f};   // [mt*2 + rowhalf]
#pragma unroll
        for (int h = 0; h < 2; h++) {        // n-tile halves: tiles 4h..4h+3
            float acc[2][4][4];
#pragma unroll
            for (int ntl = 0; ntl < 4; ntl++) {
                float2 m = *(const float2*)(mps + (4 * h + ntl) * 8 + 2 * (lane & 3));
#pragma unroll
                for (int mt = 0; mt < 2; mt++) {
                    acc[mt][ntl][0] = -m.x; acc[mt][ntl][1] = -m.y;
                    acc[mt][ntl][2] = -m.x; acc[mt][ntl][3] = -m.y;
                }
            }
#pragma unroll
            for (int kk = 0; kk < 4; kk++) {
                uint32_t bh[8];
                ldsm4(bh,     lb + sw128((brow + (2 * h)     * 16) * 128 + kk * 32 + bcol));
                ldsm4(bh + 4, lb + sw128((brow + (2 * h + 1) * 16) * 128 + kk * 32 + bcol));
#pragma unroll
                for (int mt = 0; mt < 2; mt++)
#pragma unroll
                    for (int ntl = 0; ntl < 4; ntl++)
                        mma16816(acc[mt][ntl], ah[mt][kk], bh[2 * ntl], bh[2 * ntl + 1]);
            }
#pragma unroll
            for (int mt = 0; mt < 2; mt++)
#pragma unroll
                for (int ntl = 0; ntl < 4; ntl++) {
                    q[2 * mt]     = fmaf(acc[mt][ntl][0], acc[mt][ntl][0], q[2 * mt]);
                    q[2 * mt]     = fmaf(acc[mt][ntl][1], acc[mt][ntl][1], q[2 * mt]);
                    q[2 * mt + 1] = fmaf(acc[mt][ntl][2], acc[mt][ntl][2], q[2 * mt + 1]);
                    q[2 * mt + 1] = fmaf(acc[mt][ntl][3], acc[mt][ntl][3], q[2 * mt + 1]);
                }
        }

        // quad reduce (e-dim is spread over lane&3)
#pragma unroll
        for (int j = 0; j < 4; j++) {
            q[j] += __shfl_xor_sync(0xffffffffu, q[j], 1);
            q[j] += __shfl_xor_sync(0xffffffffu, q[j], 2);
        }

        float cst = mps[64];
        if ((lane & 3) == 0) {
            int kg = kbase + k;
            int r = n0 + wid * 32 + (lane >> 2);
            out[(size_t)(r     ) * KCOMP + kg] = cst - 0.5f * q[0];
            out[(size_t)(r +  8) * KCOMP + kg] = cst - 0.5f * q[1];
            out[(size_t)(r + 16) * KCOMP + kg] = cst - 0.5f * q[2];
            out[(size_t)(r + 24) * KCOMP + kg] = cst - 0.5f * q[3];
        }
    }
}

// ---------------------------------------------------------------------------
extern "C" void kernel_launch(void* const* d_in, const int* in_sizes, int n_in,
                              void* d_out, int out_size) {
    const float* x     = (const float*)d_in[0];  // [16384, 64]
    const float* means = (const float*)d_in[1];  // [200, 64]
    const float* pc    = (const float*)d_in[2];  // [200, 64, 64]
    float* out = (float*)d_out;                  // [16384, 200]

    cudaFuncSetAttribute(gmm_hmma_kernel,
                         cudaFuncAttributeMaxDynamicSharedMemorySize, SMEM_TOTAL);

    gmm_precompute_kernel<<<KCOMP, 64>>>(means, pc);
    split_x_kernel<<<(NROWS * DF + 255) / 256, 256>>>(x);
    split_L_kernel<<<KCOMP, 256>>>(pc);

    dim3 grid(NROWS / TN, KSPLIT);   // (64, 8) = 512 CTAs, 25 comps each
    gmm_hmma_kernel<<<grid, NTHREADS, SMEM_TOTAL>>>(out);
}

// round 16
// speedup vs baseline: 5.8634x; 1.0511x over previous
#include <cuda_runtime.h>
#include <cuda_fp16.h>
#include <math.h>
#include <cstdint>

// GMM log-prob via single-pass fp16 mma.sync GEMM (fp32 accumulate).
// out[n,k] = cst_k - 0.5 * sum_e (sum_d x[n,d] L_k[d,e] - mp[k,e])^2
// N=16384, K=200, D=64.

#define KCOMP 200
#define KSPLIT 10
#define KC_PER (KCOMP / KSPLIT)   // 20
#define NPAIR  (KC_PER / 2)       // 10
#define DF    64
#define NROWS 16384
#define TN    256                 // rows per CTA (8 warps x 32 rows)
#define NTHREADS 256

// ---------------- device globals ----------------
__device__ float g_mp[KCOMP * DF];
__device__ float g_cst[KCOMP];
__device__ __align__(16) __half g_xh[NROWS * DF];
// L transposed to [k][e][d] (row = e, 64 fp16 = 128B row).
__device__ __align__(16) __half g_LT[KCOMP * DF * DF];

// ---------------- smem layout ----------------
// X (32K) | 6 stages x (L 8K + mp 256B + cst 4B + pad)
#define SM_X      0
#define SM_LBUF   32768
#define LSTRIDE   8576
#define L_MP_OFF  8192
#define NSTAGE    6
#define SMEM_TOTAL (SM_LBUF + NSTAGE * LSTRIDE)   // 84224

// ---------------- helpers ----------------
__device__ __forceinline__ uint32_t smem_u32(const void* p) {
    uint32_t a;
    asm("{ .reg .u64 t; cvta.to.shared.u64 t, %1; cvt.u32.u64 %0, t; }" : "=r"(a) : "l"(p));
    return a;
}
__device__ __forceinline__ uint32_t sw128(uint32_t off) { return off ^ ((off >> 3) & 0x70); }

__device__ __forceinline__ void cp16(uint32_t dst, const void* src) {
    asm volatile("cp.async.ca.shared.global [%0], [%1], 16;" :: "r"(dst), "l"(src) : "memory");
}
__device__ __forceinline__ void cp4(uint32_t dst, const void* src) {
    asm volatile("cp.async.ca.shared.global [%0], [%1], 4;" :: "r"(dst), "l"(src) : "memory");
}
__device__ __forceinline__ void cp_commit() { asm volatile("cp.async.commit_group;" ::: "memory"); }
__device__ __forceinline__ void cp_wait1()  { asm volatile("cp.async.wait_group 1;" ::: "memory"); }

__device__ __forceinline__ void ldsm4(uint32_t* r, uint32_t addr) {
    asm volatile("ldmatrix.sync.aligned.m8n8.x4.shared.b16 {%0,%1,%2,%3}, [%4];"
                 : "=r"(r[0]), "=r"(r[1]), "=r"(r[2]), "=r"(r[3]) : "r"(addr));
}
__device__ __forceinline__ void mma16816(float* c, const uint32_t* a, uint32_t b0, uint32_t b1) {
    asm volatile("mma.sync.aligned.m16n8k16.row.col.f32.f16.f16.f32 "
                 "{%0,%1,%2,%3}, {%4,%5,%6,%7}, {%8,%9}, {%0,%1,%2,%3};"
                 : "+f"(c[0]), "+f"(c[1]), "+f"(c[2]), "+f"(c[3])
                 : "r"(a[0]), "r"(a[1]), "r"(a[2]), "r"(a[3]), "r"(b0), "r"(b1));
}

// ---------------- fused precompute kernel ----------------
// blocks [0,4096): x -> fp16.  blocks [4096,4296): per-k L transpose + mp + cst.
__global__ void gmm_prep_kernel(const float* __restrict__ x,
                                const float* __restrict__ means,
                                const float* __restrict__ pc) {
    const int b = blockIdx.x;
    const int tid = threadIdx.x;
    if (b < 4096) {
        int i = b * 256 + tid;             // exactly NROWS*DF = 1,048,576
        g_xh[i] = __float2half(x[i]);
        return;
    }
    const int k = b - 4096;
    const float* L = pc + (size_t)k * DF * DF;
#pragma unroll
    for (int idx = tid; idx < DF * DF; idx += 256) {
        int d = idx >> 6, e = idx & 63;
        g_LT[(size_t)k * DF * DF + e * DF + d] = __float2half(L[idx]);
    }
    __shared__ float s[2];
    if (tid < 64) {
        const int e = tid;
        const float* mu = means + k * DF;
        float acc = 0.0f;
#pragma unroll 8
        for (int d = 0; d < DF; ++d) acc = fmaf(mu[d], L[d * DF + e], acc);
        g_mp[k * DF + e] = acc;
        float lg = logf(L[e * DF + e]);
#pragma unroll
        for (int off = 16; off; off >>= 1) lg += __shfl_xor_sync(0xffffffffu, lg, off);
        if ((tid & 31) == 0) s[tid >> 5] = lg;
    }
    __syncthreads();
    if (tid == 0) g_cst[k] = (s[0] + s[1]) - 0.5f * DF * 1.8378770664093453f;
}

// ---------------- main HMMA kernel ----------------
__device__ __forceinline__ void load_ltile(uint32_t sb, int kg, int st) {
    uint32_t base = sb + SM_LBUF + st * LSTRIDE;
    const char* sh = (const char*)g_LT + (size_t)kg * DF * DF * 2;
    int tid = threadIdx.x;
#pragma unroll
    for (int i = 0; i < 2; i++) {
        int c = tid + i * NTHREADS;          // 0..511 chunks of 16B (8 KB)
        cp16(base + sw128((uint32_t)c * 16), sh + c * 16);
    }
    if (tid < 16)
        cp16(base + L_MP_OFF + tid * 16, (const char*)g_mp + (size_t)kg * DF * 4 + tid * 16);
    if (tid == 16)
        cp4(base + L_MP_OFF + 256, (const char*)g_cst + (size_t)kg * 4);
}

__device__ __forceinline__ void load_pair(uint32_t sb, int kbase, int pr) {
    int s0 = (2 * pr) % NSTAGE;
    load_ltile(sb, kbase + 2 * pr,     s0);
    load_ltile(sb, kbase + 2 * pr + 1, s0 + 1);
}

__global__ void __launch_bounds__(NTHREADS, 2)
gmm_hmma_kernel(float* __restrict__ out) {
    extern __shared__ __align__(1024) char smem[];
    uint32_t sb = smem_u32(smem);
    const int tid = threadIdx.x, wid = tid >> 5, lane = tid & 31;
    const int n0 = blockIdx.x * TN;
    const int kbase = blockIdx.y * KC_PER;

    // prologue: X tile (32 KB) + pair 0 -> G0 ; pair 1 -> G1
    {
        const char* xh = (const char*)g_xh + (size_t)n0 * DF * 2;
#pragma unroll
        for (int i = 0; i < 8; i++) {
            int c = tid + i * NTHREADS;      // 0..2047 chunks of 16B
            cp16(sb + SM_X + sw128((uint32_t)c * 16), xh + c * 16);
        }
    }
    load_pair(sb, kbase, 0);
    cp_commit();                 // G0 = X + pair0
    load_pair(sb, kbase, 1);
    cp_commit();                 // G1 = pair1

    uint32_t ah[2][4][4];        // [m-tile][k-step][frag]
    const uint32_t brow = (lane & 7) + ((lane >> 4) << 3);
    const uint32_t bcol = ((lane >> 3) & 1) * 16;

    for (int p = 0; p < NPAIR; ++p) {
        cp_wait1();              // pair p resident (this thread's copies)
        __syncthreads();         // visibility to all + all warps done with pair p-1

        // prefetch pair p+2 (overwrites pair p-1's stages; safe after sync)
        if (p + 2 < NPAIR) load_pair(sb, kbase, p + 2);
        cp_commit();             // empty group at tail keeps the wait invariant

        if (p == 0) {            // A fragments: 2 m-tiles x 4 k-steps, loaded once
            uint32_t acol = (uint32_t)((lane >> 4) * 16);
#pragma unroll
            for (int mt = 0; mt < 2; mt++) {
                uint32_t arow = (uint32_t)(wid * 32 + mt * 16 + (lane & 15));
#pragma unroll
                for (int kk = 0; kk < 4; kk++)
                    ldsm4(ah[mt][kk], sb + SM_X + sw128(arow * 128 + kk * 32 + acol));
            }
        }

#pragma unroll
        for (int kk2 = 0; kk2 < 2; ++kk2) {      // the 2 comps of this pair (no barrier)
            const int k = 2 * p + kk2;
            const int st = (2 * p) % NSTAGE + kk2;
            const uint32_t lb = sb + SM_LBUF + st * LSTRIDE;
            const float* mps = (const float*)(smem + SM_LBUF + st * LSTRIDE + L_MP_OFF);

            float q[4] = {0.f, 0.f, 0.f, 0.f};   // [2*mt + rowhalf]
#pragma unroll
            for (int h = 0; h < 2; h++) {        // n-tile halves: tiles 4h..4h+3
                float acc[2][4][4];
#pragma unroll
                for (int ntl = 0; ntl < 4; ntl++) {
                    float2 m = *(const float2*)(mps + (4 * h + ntl) * 8 + 2 * (lane & 3));
#pragma unroll
                    for (int mt = 0; mt < 2; mt++) {
                        acc[mt][ntl][0] = -m.x; acc[mt][ntl][1] = -m.y;
                        acc[mt][ntl][2] = -m.x; acc[mt][ntl][3] = -m.y;
                    }
                }
#pragma unroll
                for (int kk = 0; kk < 4; kk++) {
                    uint32_t bh[8];
                    ldsm4(bh,     lb + sw128((brow + (2 * h)     * 16) * 128 + kk * 32 + bcol));
                    ldsm4(bh + 4, lb + sw128((brow + (2 * h + 1) * 16) * 128 + kk * 32 + bcol));
#pragma unroll
                    for (int mt = 0; mt < 2; mt++)
#pragma unroll
                        for (int ntl = 0; ntl < 4; ntl++)
                            mma16816(acc[mt][ntl], ah[mt][kk], bh[2 * ntl], bh[2 * ntl + 1]);
                }
#pragma unroll
                for (int mt = 0; mt < 2; mt++)
#pragma unroll
                    for (int ntl = 0; ntl < 4; ntl++) {
                        q[2 * mt]     = fmaf(acc[mt][ntl][0], acc[mt][ntl][0], q[2 * mt]);
                        q[2 * mt]     = fmaf(acc[mt][ntl][1], acc[mt][ntl][1], q[2 * mt]);
                        q[2 * mt + 1] = fmaf(acc[mt][ntl][2], acc[mt][ntl][2], q[2 * mt + 1]);
                        q[2 * mt + 1] = fmaf(acc[mt][ntl][3], acc[mt][ntl][3], q[2 * mt + 1]);
                    }
            }

            // quad reduce with lane-index redistribution: lane ends with q[lane&3]
            const int p1 = lane & 1, p2 = (lane >> 1) & 1;
            float u0 = p1 ? q[1] : q[0], u0s = p1 ? q[0] : q[1];
            float u1 = p1 ? q[3] : q[2], u1s = p1 ? q[2] : q[3];
            u0 += __shfl_xor_sync(0xffffffffu, u0s, 1);
            u1 += __shfl_xor_sync(0xffffffffu, u1s, 1);
            float w = p2 ? u1 : u0, ws = p2 ? u0 : u1;
            w += __shfl_xor_sync(0xffffffffu, ws, 2);

            const float cst = mps[64];
            const int kg = kbase + k;
            const int r = n0 + wid * 32 + (lane >> 2) + 8 * (lane & 3);
            out[(size_t)r * KCOMP + kg] = cst - 0.5f * w;
        }
    }
}

// ---------------------------------------------------------------------------
extern "C" void kernel_launch(void* const* d_in, const int* in_sizes, int n_in,
                              void* d_out, int out_size) {
    const float* x     = (const float*)d_in[0];  // [16384, 64]
    const float* means = (const float*)d_in[1];  // [200, 64]
    const float* pc    = (const float*)d_in[2];  // [200, 64, 64]
    float* out = (float*)d_out;                  // [16384, 200]

    cudaFuncSetAttribute(gmm_hmma_kernel,
                         cudaFuncAttributeMaxDynamicSharedMemorySize, SMEM_TOTAL);

    gmm_prep_kernel<<<4096 + KCOMP, 256>>>(x, means, pc);

    dim3 grid(NROWS / TN, KSPLIT);   // (64, 10) = 640 CTAs, 20 comps each
    gmm_hmma_kernel<<<grid, NTHREADS, SMEM_TOTAL>>>(out);
}

// round 17
// speedup vs baseline: 6.2110x; 1.0593x over previous
#include <cuda_runtime.h>
#include <cuda_fp16.h>
#include <math.h>
#include <cstdint>

// GMM log-prob via single-pass fp16 mma.sync GEMM (fp32 accumulate).
// out[n,k] = cst_k - 0.5 * sum_e (sum_d x[n,d] L_k[d,e] - mp[k,e])^2
// N=16384, K=200, D=64.

#define KCOMP 200
#define KSPLIT 20
#define KC_PER (KCOMP / KSPLIT)   // 10
#define NPAIR  (KC_PER / 2)       // 5
#define DF    64
#define NROWS 16384
#define TN    128                 // rows per CTA (4 warps x 32 rows)
#define NTHREADS 128

// ---------------- device globals ----------------
__device__ float g_mp[KCOMP * DF];
__device__ float g_cst[KCOMP];
__device__ __align__(16) __half g_xh[NROWS * DF];
// L transposed to [k][e][d] (row = e, 64 fp16 = 128B row).
__device__ __align__(16) __half g_LT[KCOMP * DF * DF];

// ---------------- smem layout ----------------
// [0, 16384)        : X tile (alive only until p==0 A-frag read)
//                     then reused as L stage slots 4,5 (2 x 8448 = 16896 <= 16896)
// [16896, 50688)    : L stage slots 0..3 (4 x 8448)
// Each slot: L 8192B + mp 256B.
#define SM_X        0
#define LSTRIDE     8448
#define L_MP_OFF    8192
#define SLOT03_BASE 16896
#define NSTAGE      6
#define SMEM_TOTAL  (SLOT03_BASE + 4 * LSTRIDE)   // 50688

// ---------------- helpers ----------------
__device__ __forceinline__ uint32_t smem_u32(const void* p) {
    uint32_t a;
    asm("{ .reg .u64 t; cvta.to.shared.u64 t, %1; cvt.u32.u64 %0, t; }" : "=r"(a) : "l"(p));
    return a;
}
__device__ __forceinline__ uint32_t sw128(uint32_t off) { return off ^ ((off >> 3) & 0x70); }
__device__ __forceinline__ uint32_t stage_off(int st) {
    return (st < 4) ? (uint32_t)(SLOT03_BASE + st * LSTRIDE)
                    : (uint32_t)((st - 4) * LSTRIDE);
}

__device__ __forceinline__ void cp16(uint32_t dst, const void* src) {
    asm volatile("cp.async.ca.shared.global [%0], [%1], 16;" :: "r"(dst), "l"(src) : "memory");
}
__device__ __forceinline__ void cp_commit() { asm volatile("cp.async.commit_group;" ::: "memory"); }
__device__ __forceinline__ void cp_wait1()  { asm volatile("cp.async.wait_group 1;" ::: "memory"); }

__device__ __forceinline__ void ldsm4(uint32_t* r, uint32_t addr) {
    asm volatile("ldmatrix.sync.aligned.m8n8.x4.shared.b16 {%0,%1,%2,%3}, [%4];"
                 : "=r"(r[0]), "=r"(r[1]), "=r"(r[2]), "=r"(r[3]) : "r"(addr));
}
__device__ __forceinline__ void mma16816(float* c, const uint32_t* a, uint32_t b0, uint32_t b1) {
    asm volatile("mma.sync.aligned.m16n8k16.row.col.f32.f16.f16.f32 "
                 "{%0,%1,%2,%3}, {%4,%5,%6,%7}, {%8,%9}, {%0,%1,%2,%3};"
                 : "+f"(c[0]), "+f"(c[1]), "+f"(c[2]), "+f"(c[3])
                 : "r"(a[0]), "r"(a[1]), "r"(a[2]), "r"(a[3]), "r"(b0), "r"(b1));
}

// ---------------- fused precompute kernel ----------------
__global__ void gmm_prep_kernel(const float* __restrict__ x,
                                const float* __restrict__ means,
                                const float* __restrict__ pc) {
    const int b = blockIdx.x;
    const int tid = threadIdx.x;
    if (b < 4096) {
        int i = b * 256 + tid;             // exactly NROWS*DF
        g_xh[i] = __float2half(x[i]);
        return;
    }
    const int k = b - 4096;
    const float* L = pc + (size_t)k * DF * DF;
#pragma unroll
    for (int idx = tid; idx < DF * DF; idx += 256) {
        int d = idx >> 6, e = idx & 63;
        g_LT[(size_t)k * DF * DF + e * DF + d] = __float2half(L[idx]);
    }
    __shared__ float s[2];
    if (tid < 64) {
        const int e = tid;
        const float* mu = means + k * DF;
        float acc = 0.0f;
#pragma unroll 8
        for (int d = 0; d < DF; ++d) acc = fmaf(mu[d], L[d * DF + e], acc);
        g_mp[k * DF + e] = acc;
        float lg = logf(L[e * DF + e]);
#pragma unroll
        for (int off = 16; off; off >>= 1) lg += __shfl_xor_sync(0xffffffffu, lg, off);
        if ((tid & 31) == 0) s[tid >> 5] = lg;
    }
    __syncthreads();
    if (tid == 0) g_cst[k] = (s[0] + s[1]) - 0.5f * DF * 1.8378770664093453f;
}

// ---------------- main HMMA kernel ----------------
__device__ __forceinline__ void load_ltile(uint32_t sb, int kg, int st) {
    uint32_t base = sb + stage_off(st);
    const char* sh = (const char*)g_LT + (size_t)kg * DF * DF * 2;
    int tid = threadIdx.x;
#pragma unroll
    for (int i = 0; i < 4; i++) {
        int c = tid + i * NTHREADS;          // 0..511 chunks of 16B (8 KB)
        cp16(base + sw128((uint32_t)c * 16), sh + c * 16);
    }
    if (tid < 16)
        cp16(base + L_MP_OFF + tid * 16, (const char*)g_mp + (size_t)kg * DF * 4 + tid * 16);
}

__device__ __forceinline__ void load_pair(uint32_t sb, int kbase, int pr) {
    int s0 = (2 * pr) % NSTAGE;
    load_ltile(sb, kbase + 2 * pr,     s0);
    load_ltile(sb, kbase + 2 * pr + 1, s0 + 1);
}

__global__ void __launch_bounds__(NTHREADS, 4)
gmm_hmma_kernel(float* __restrict__ out) {
    extern __shared__ __align__(1024) char smem[];
    uint32_t sb = smem_u32(smem);
    const int tid = threadIdx.x, wid = tid >> 5, lane = tid & 31;
    const int n0 = blockIdx.x * TN;
    const int kbase = blockIdx.y * KC_PER;

    // prologue: X tile (16 KB) + pair 0 -> G0 ; pair 1 -> G1
    {
        const char* xh = (const char*)g_xh + (size_t)n0 * DF * 2;
#pragma unroll
        for (int i = 0; i < 8; i++) {
            int c = tid + i * NTHREADS;      // 0..1023 chunks of 16B
            cp16(sb + SM_X + sw128((uint32_t)c * 16), xh + c * 16);
        }
    }
    load_pair(sb, kbase, 0);
    cp_commit();                 // G0 = X + pair0 (slots 0,1)
    load_pair(sb, kbase, 1);
    cp_commit();                 // G1 = pair1 (slots 2,3)

    uint32_t ah[2][4][4];        // [m-tile][k-step][frag]
    const uint32_t brow = (lane & 7) + ((lane >> 4) << 3);
    const uint32_t bcol = ((lane >> 3) & 1) * 16;

    for (int p = 0; p < NPAIR; ++p) {
        cp_wait1();              // pair p resident (this thread's copies)
        __syncthreads();         // visibility + all warps done with pair p-1

        if (p == 0) {            // A fragments: 2 m-tiles x 4 k-steps, read once
            uint32_t acol = (uint32_t)((lane >> 4) * 16);
#pragma unroll
            for (int mt = 0; mt < 2; mt++) {
                uint32_t arow = (uint32_t)(wid * 32 + mt * 16 + (lane & 15));
#pragma unroll
                for (int kk = 0; kk < 4; kk++)
                    ldsm4(ah[mt][kk], sb + SM_X + sw128(arow * 128 + kk * 32 + acol));
            }
            __syncthreads();     // X fully consumed before slots 4,5 (X region) get written
        }

        // prefetch pair p+2 (slots of pair p-1, already consumed; at p==0 -> X region)
        if (p + 2 < NPAIR) load_pair(sb, kbase, p + 2);
        cp_commit();             // empty group at tail keeps the wait invariant

#pragma unroll
        for (int kk2 = 0; kk2 < 2; ++kk2) {      // the 2 comps of this pair (no barrier)
            const int k = 2 * p + kk2;
            const int kg = kbase + k;
            const int st = (2 * p) % NSTAGE + kk2;
            const uint32_t lb = sb + stage_off(st);
            const float* mps = (const float*)(smem + stage_off(st) + L_MP_OFF);
            const float cst = __ldg(&g_cst[kg]);   // issued early, used at store

            float q[4] = {0.f, 0.f, 0.f, 0.f};     // [2*mt + rowhalf]
#pragma unroll
            for (int h = 0; h < 2; h++) {          // n-tile halves: tiles 4h..4h+3
                float acc[2][4][4];
#pragma unroll
                for (int ntl = 0; ntl < 4; ntl++) {
                    float2 m = *(const float2*)(mps + (4 * h + ntl) * 8 + 2 * (lane & 3));
#pragma unroll
                    for (int mt = 0; mt < 2; mt++) {
                        acc[mt][ntl][0] = -m.x; acc[mt][ntl][1] = -m.y;
                        acc[mt][ntl][2] = -m.x; acc[mt][ntl][3] = -m.y;
                    }
                }
#pragma unroll
                for (int kk = 0; kk < 4; kk++) {
                    uint32_t bh[8];
                    ldsm4(bh,     lb + sw128((brow + (2 * h)     * 16) * 128 + kk * 32 + bcol));
                    ldsm4(bh + 4, lb + sw128((brow + (2 * h + 1) * 16) * 128 + kk * 32 + bcol));
#pragma unroll
                    for (int mt = 0; mt < 2; mt++)
#pragma unroll
                        for (int ntl = 0; ntl < 4; ntl++)
                            mma16816(acc[mt][ntl], ah[mt][kk], bh[2 * ntl], bh[2 * ntl + 1]);
                }
#pragma unroll
                for (int mt = 0; mt < 2; mt++)
#pragma unroll
                    for (int ntl = 0; ntl < 4; ntl++) {
                        q[2 * mt]     = fmaf(acc[mt][ntl][0], acc[mt][ntl][0], q[2 * mt]);
                        q[2 * mt]     = fmaf(acc[mt][ntl][1], acc[mt][ntl][1], q[2 * mt]);
                        q[2 * mt + 1] = fmaf(acc[mt][ntl][2], acc[mt][ntl][2], q[2 * mt + 1]);
                        q[2 * mt + 1] = fmaf(acc[mt][ntl][3], acc[mt][ntl][3], q[2 * mt + 1]);
                    }
            }

            // quad reduce with lane-index redistribution: lane ends with q[lane&3]
            const int p1 = lane & 1, p2 = (lane >> 1) & 1;
            float u0 = p1 ? q[1] : q[0], u0s = p1 ? q[0] : q[1];
            float u1 = p1 ? q[3] : q[2], u1s = p1 ? q[2] : q[3];
            u0 += __shfl_xor_sync(0xffffffffu, u0s, 1);
            u1 += __shfl_xor_sync(0xffffffffu, u1s, 1);
            float w = p2 ? u1 : u0, ws = p2 ? u0 : u1;
            w += __shfl_xor_sync(0xffffffffu, ws, 2);

            const int r = n0 + wid * 32 + (lane >> 2) + 8 * (lane & 3);
            out[(size_t)r * KCOMP + kg] = cst - 0.5f * w;
        }
    }
}

// ---------------------------------------------------------------------------
extern "C" void kernel_launch(void* const* d_in, const int* in_sizes, int n_in,
                              void* d_out, int out_size) {
    const float* x     = (const float*)d_in[0];  // [16384, 64]
    const float* means = (const float*)d_in[1];  // [200, 64]
    const float* pc    = (const float*)d_in[2];  // [200, 64, 64]
    float* out = (float*)d_out;                  // [16384, 200]

    cudaFuncSetAttribute(gmm_hmma_kernel,
                         cudaFuncAttributeMaxDynamicSharedMemorySize, SMEM_TOTAL);

    gmm_prep_kernel<<<4096 + KCOMP, 256>>>(x, means, pc);

    dim3 grid(NROWS / TN, KSPLIT);   // (128, 20) = 2560 CTAs, 10 comps each
    gmm_hmma_kernel<<<grid, NTHREADS, SMEM_TOTAL>>>(out);
}